// round 3
// baseline (speedup 1.0000x reference)
#include <cuda_runtime.h>
#include <cstdint>

typedef unsigned long long ull;

#define N_ROWS 32768
#define K_CODES 4096
#define D_DIM   256

#define BM 128          // rows per block tile
#define BN 128          // codes per inner chunk
#define CHUNK 512       // codes per work item
#define BK 8            // d per smem stage
#define XROW 260        // duplicated X row stride in floats (16B-aligned rows)
#define CROW 132        // C row stride in floats (16B-aligned rows)

// Scratch (no allocations allowed)
__device__ float g_cc[K_CODES];
__device__ float g_xx[N_ROWS];
__device__ ull   g_pack[N_ROWS];   // (dist_bits<<32)|code, atomicMin-merged

// ---------------------------------------------------------------------------
// packed f32x2 helpers (FFMA2 path)
// ---------------------------------------------------------------------------
__device__ __forceinline__ void unpack2(ull v, float& lo, float& hi) {
    asm("mov.b64 {%0, %1}, %2;" : "=f"(lo), "=f"(hi) : "l"(v));
}
__device__ __forceinline__ void fma2(ull& d, ull a, ull b) {
    asm("fma.rn.f32x2 %0, %1, %2, %0;" : "+l"(d) : "l"(a), "l"(b));
}

// ---------------------------------------------------------------------------
// Kernel 1: row norms (reference order: multiply, then sequential adds, no
// fma contraction) + reset of the packed argmin array.
// ---------------------------------------------------------------------------
__global__ void norms_kernel(const float* __restrict__ x,
                             const float* __restrict__ cb) {
    int i = blockIdx.x * blockDim.x + threadIdx.x;
    if (i < K_CODES) {
        const float4* r = reinterpret_cast<const float4*>(cb) + (size_t)i * (D_DIM / 4);
        float s = 0.0f;
#pragma unroll
        for (int d = 0; d < D_DIM / 4; ++d) {
            float4 v = r[d];
            s = __fadd_rn(s, __fmul_rn(v.x, v.x));
            s = __fadd_rn(s, __fmul_rn(v.y, v.y));
            s = __fadd_rn(s, __fmul_rn(v.z, v.z));
            s = __fadd_rn(s, __fmul_rn(v.w, v.w));
        }
        g_cc[i] = s;
    }
    if (i < N_ROWS) {
        g_pack[i] = ~0ULL;
        const float4* r = reinterpret_cast<const float4*>(x) + (size_t)i * (D_DIM / 4);
        float s = 0.0f;
#pragma unroll
        for (int d = 0; d < D_DIM / 4; ++d) {
            float4 v = r[d];
            s = __fadd_rn(s, __fmul_rn(v.x, v.x));
            s = __fadd_rn(s, __fmul_rn(v.y, v.y));
            s = __fadd_rn(s, __fmul_rn(v.z, v.z));
            s = __fadd_rn(s, __fmul_rn(v.w, v.w));
        }
        g_xx[i] = s;
    }
}

// ---------------------------------------------------------------------------
// Kernel 2: fused GEMM (X @ C^T) + argmin over a work item.
// Item = 128 rows x 512 codes; grid = (N/128)*(K/512) = 2048 items.
// Per-thread 8x8 micro-tile as 32 packed f32x2 accumulators; X tile stored
// DUPLICATED in smem so LDS.128 directly yields (a,a) operand pairs (no MOVs).
// Accumulation over d strictly sequential -> bitwise-stable fp32 chain.
// dist replicates reference rounding: fl(fl(xx+cc) + (-2*s)); dist >= 0.
// Merge across items via atomicMin of (dist_bits<<32 | idx): min dist, then
// min index on exact ties == first-occurrence argmin.
// ---------------------------------------------------------------------------
struct __align__(16) Smem {
    union {
        struct {
            float Xd[2][BK][XROW];   // duplicated: Xd[k][2r]=Xd[k][2r+1]=x
            float Cs[2][BK][CROW];
        } t;
        struct {
            float rd[BM][16];
            int   ri[BM][16];
        } r;
    } u;
    float sxx[BM];
};

__global__ __launch_bounds__(256, 2)
void vq_argmin_kernel(const float* __restrict__ x,
                      const float* __restrict__ cb) {
    __shared__ Smem sm;

    const int tid = threadIdx.x;
    const int tx  = tid & 15;   // code group (8 codes)
    const int ty  = tid >> 4;   // row  group (8 rows)

    const int rowBase   = (blockIdx.x >> 3) * BM;
    const int chunkBase = (blockIdx.x & 7) * CHUNK;

    if (tid < BM) sm.sxx[tid] = g_xx[rowBase + tid];

    float best[8];
    int   bidx[8];
#pragma unroll
    for (int i = 0; i < 8; ++i) { best[i] = 3.4028235e38f; bidx[i] = 0; }

    const float4* x4  = reinterpret_cast<const float4*>(x);
    const float4* cb4 = reinterpret_cast<const float4*>(cb);

    // loader: per stage, 128 rows x 8 d = 256 float4 each for X and C
    const int lrow = tid >> 1;        // 0..127
    const int lseg = tid & 1;         // which float4 within the 8-d slab

    for (int kt = 0; kt < CHUNK / BN; ++kt) {
        const int codeBase = chunkBase + kt * BN;

        ull acc[8][4];
#pragma unroll
        for (int i = 0; i < 8; ++i)
#pragma unroll
            for (int j = 0; j < 4; ++j) acc[i][j] = 0ULL;

        // prologue: stage 0
        {
            float4 vx = x4[(size_t)(rowBase + lrow) * (D_DIM / 4) + lseg];
            float4 vc = cb4[(size_t)(codeBase + lrow) * (D_DIM / 4) + lseg];
            *reinterpret_cast<float2*>(&sm.u.t.Xd[0][lseg * 4 + 0][2 * lrow]) = make_float2(vx.x, vx.x);
            *reinterpret_cast<float2*>(&sm.u.t.Xd[0][lseg * 4 + 1][2 * lrow]) = make_float2(vx.y, vx.y);
            *reinterpret_cast<float2*>(&sm.u.t.Xd[0][lseg * 4 + 2][2 * lrow]) = make_float2(vx.z, vx.z);
            *reinterpret_cast<float2*>(&sm.u.t.Xd[0][lseg * 4 + 3][2 * lrow]) = make_float2(vx.w, vx.w);
            sm.u.t.Cs[0][lseg * 4 + 0][lrow] = vc.x;
            sm.u.t.Cs[0][lseg * 4 + 1][lrow] = vc.y;
            sm.u.t.Cs[0][lseg * 4 + 2][lrow] = vc.z;
            sm.u.t.Cs[0][lseg * 4 + 3][lrow] = vc.w;
        }
        __syncthreads();

        for (int dc = 0; dc < D_DIM / BK; ++dc) {
            const int cur = dc & 1;
            if (dc + 1 < D_DIM / BK) {
                const int nb = cur ^ 1;
                float4 vx = x4[(size_t)(rowBase + lrow) * (D_DIM / 4) + (dc + 1) * 2 + lseg];
                float4 vc = cb4[(size_t)(codeBase + lrow) * (D_DIM / 4) + (dc + 1) * 2 + lseg];
                *reinterpret_cast<float2*>(&sm.u.t.Xd[nb][lseg * 4 + 0][2 * lrow]) = make_float2(vx.x, vx.x);
                *reinterpret_cast<float2*>(&sm.u.t.Xd[nb][lseg * 4 + 1][2 * lrow]) = make_float2(vx.y, vx.y);
                *reinterpret_cast<float2*>(&sm.u.t.Xd[nb][lseg * 4 + 2][2 * lrow]) = make_float2(vx.z, vx.z);
                *reinterpret_cast<float2*>(&sm.u.t.Xd[nb][lseg * 4 + 3][2 * lrow]) = make_float2(vx.w, vx.w);
                sm.u.t.Cs[nb][lseg * 4 + 0][lrow] = vc.x;
                sm.u.t.Cs[nb][lseg * 4 + 1][lrow] = vc.y;
                sm.u.t.Cs[nb][lseg * 4 + 2][lrow] = vc.z;
                sm.u.t.Cs[nb][lseg * 4 + 3][lrow] = vc.w;
            }

#pragma unroll
            for (int kk = 0; kk < BK; ++kk) {
                const ulonglong2 a01 = *reinterpret_cast<const ulonglong2*>(&sm.u.t.Xd[cur][kk][ty * 16]);
                const ulonglong2 a23 = *reinterpret_cast<const ulonglong2*>(&sm.u.t.Xd[cur][kk][ty * 16 + 4]);
                const ulonglong2 a45 = *reinterpret_cast<const ulonglong2*>(&sm.u.t.Xd[cur][kk][ty * 16 + 8]);
                const ulonglong2 a67 = *reinterpret_cast<const ulonglong2*>(&sm.u.t.Xd[cur][kk][ty * 16 + 12]);
                const ulonglong2 b01 = *reinterpret_cast<const ulonglong2*>(&sm.u.t.Cs[cur][kk][tx * 8]);
                const ulonglong2 b23 = *reinterpret_cast<const ulonglong2*>(&sm.u.t.Cs[cur][kk][tx * 8 + 4]);
                const ull aa0 = a01.x, aa1 = a01.y, aa2 = a23.x, aa3 = a23.y;
                const ull aa4 = a45.x, aa5 = a45.y, aa6 = a67.x, aa7 = a67.y;
                const ull bb0 = b01.x, bb1 = b01.y, bb2 = b23.x, bb3 = b23.y;
                fma2(acc[0][0], aa0, bb0); fma2(acc[0][1], aa0, bb1); fma2(acc[0][2], aa0, bb2); fma2(acc[0][3], aa0, bb3);
                fma2(acc[1][0], aa1, bb0); fma2(acc[1][1], aa1, bb1); fma2(acc[1][2], aa1, bb2); fma2(acc[1][3], aa1, bb3);
                fma2(acc[2][0], aa2, bb0); fma2(acc[2][1], aa2, bb1); fma2(acc[2][2], aa2, bb2); fma2(acc[2][3], aa2, bb3);
                fma2(acc[3][0], aa3, bb0); fma2(acc[3][1], aa3, bb1); fma2(acc[3][2], aa3, bb2); fma2(acc[3][3], aa3, bb3);
                fma2(acc[4][0], aa4, bb0); fma2(acc[4][1], aa4, bb1); fma2(acc[4][2], aa4, bb2); fma2(acc[4][3], aa4, bb3);
                fma2(acc[5][0], aa5, bb0); fma2(acc[5][1], aa5, bb1); fma2(acc[5][2], aa5, bb2); fma2(acc[5][3], aa5, bb3);
                fma2(acc[6][0], aa6, bb0); fma2(acc[6][1], aa6, bb1); fma2(acc[6][2], aa6, bb2); fma2(acc[6][3], aa6, bb3);
                fma2(acc[7][0], aa7, bb0); fma2(acc[7][1], aa7, bb1); fma2(acc[7][2], aa7, bb2); fma2(acc[7][3], aa7, bb3);
            }
            __syncthreads();
        }

        // epilogue: distances + running argmin (ascending code order)
#pragma unroll
        for (int j = 0; j < 4; ++j) {
            const int c0 = codeBase + tx * 8 + j * 2;
            const float cc0 = g_cc[c0];
            const float cc1 = g_cc[c0 + 1];
#pragma unroll
            for (int i = 0; i < 8; ++i) {
                float s0, s1;
                unpack2(acc[i][j], s0, s1);
                const float xxv = sm.sxx[ty * 8 + i];
                const float d0 = __fadd_rn(__fadd_rn(xxv, cc0), __fmul_rn(-2.0f, s0));
                const float d1 = __fadd_rn(__fadd_rn(xxv, cc1), __fmul_rn(-2.0f, s1));
                if (d0 < best[i]) { best[i] = d0; bidx[i] = c0; }
                if (d1 < best[i]) { best[i] = d1; bidx[i] = c0 + 1; }
            }
        }
    }

    // cross-thread reduction per row, then global merge
    __syncthreads();
#pragma unroll
    for (int i = 0; i < 8; ++i) {
        sm.u.r.rd[ty * 8 + i][tx] = best[i];
        sm.u.r.ri[ty * 8 + i][tx] = bidx[i];
    }
    __syncthreads();
    if (tid < BM) {
        float b  = sm.u.r.rd[tid][0];
        int   bi = sm.u.r.ri[tid][0];
#pragma unroll
        for (int t = 1; t < 16; ++t) {
            const float d  = sm.u.r.rd[tid][t];
            const int   di = sm.u.r.ri[tid][t];
            if (d < b || (d == b && di < bi)) { b = d; bi = di; }
        }
        // dist >= 0 (xx ~ 256 dominates), so float bits are order-preserving
        const ull key = ((ull)__float_as_uint(b) << 32) | (unsigned)bi;
        atomicMin(&g_pack[rowBase + tid], key);
    }
}

// ---------------------------------------------------------------------------
// Kernel 3: out = x + (codebook[best] - x), replicating reference rounding.
// ---------------------------------------------------------------------------
__global__ void gather_kernel(const float* __restrict__ x,
                              const float* __restrict__ cb,
                              float* __restrict__ out) {
    const int idx = blockIdx.x * blockDim.x + threadIdx.x;  // over N*64 float4
    const int row = idx >> 6;
    const int seg = idx & 63;
    const int code = (int)(unsigned)(g_pack[row] & 0xFFFFFFFFULL);
    float4 c = reinterpret_cast<const float4*>(cb)[(size_t)code * 64 + seg];
    float4 v = reinterpret_cast<const float4*>(x)[idx];
    float4 o;
    o.x = __fadd_rn(v.x, __fsub_rn(c.x, v.x));
    o.y = __fadd_rn(v.y, __fsub_rn(c.y, v.y));
    o.z = __fadd_rn(v.z, __fsub_rn(c.z, v.z));
    o.w = __fadd_rn(v.w, __fsub_rn(c.w, v.w));
    reinterpret_cast<float4*>(out)[idx] = o;
}

// ---------------------------------------------------------------------------
extern "C" void kernel_launch(void* const* d_in, const int* in_sizes, int n_in,
                              void* d_out, int out_size) {
    const float* x  = (const float*)d_in[0];
    const float* cb = (const float*)d_in[1];
    if (n_in >= 2 && in_sizes[0] == K_CODES * D_DIM && in_sizes[1] == N_ROWS * D_DIM) {
        const float* t = x; x = cb; cb = t;
    }
    float* out = (float*)d_out;

    norms_kernel<<<(N_ROWS + 255) / 256, 256>>>(x, cb);
    vq_argmin_kernel<<<(N_ROWS / BM) * (K_CODES / CHUNK), 256>>>(x, cb);
    gather_kernel<<<(N_ROWS * 64) / 256, 256>>>(x, cb, out);
}

// round 7
// speedup vs baseline: 3.1996x; 3.1996x over previous
#include <cuda_runtime.h>
#include <cuda_bf16.h>
#include <cstdint>

typedef unsigned long long ull;

#define N_ROWS 32768
#define K_CODES 4096
#define D_DIM   256

#define SCR_M 128                 // rows per screening CTA
#define SCR_NC 64                 // codes per chunk
#define SCR_NCHUNK (K_CODES / SCR_NC)
#define ROW_B 528                 // smem row stride bytes (264 bf16): conflict-free ldmatrix
#define A_BYTES (SCR_M * ROW_B)   // 67584
#define B_BYTES (SCR_NC * ROW_B)  // 33792
#define CAND_CAP 64
#define MARGIN 4e-4f
#define FINF 3.4028235e38f

// Scratch (device globals; no allocation APIs allowed)
__device__ float g_cc[K_CODES];
__device__ float g_xx[N_ROWS];
__device__ ull   g_pack[N_ROWS];
__device__ __align__(128) unsigned g_cbb[K_CODES * D_DIM / 2];  // codebook bf16x2
__device__ __align__(128) unsigned g_xbb[N_ROWS * D_DIM / 2];   // x bf16x2
__device__ int   g_cand[N_ROWS * CAND_CAP];
__device__ int   g_cnt[N_ROWS];

// ---------------------------------------------------------------------------
// helpers (all base-ISA: portable to plain sm_100 target; NO tcgen05)
// ---------------------------------------------------------------------------
__device__ __forceinline__ uint32_t smem_u32(const void* p) {
    uint32_t a;
    asm("{ .reg .u64 t; cvta.to.shared.u64 t, %1; cvt.u32.u64 %0, t; }" : "=r"(a) : "l"(p));
    return a;
}
__device__ __forceinline__ uint32_t pack_bf16x2(float lo, float hi) {
    uint32_t r;   // cvt d, a, b packs a into high half, b into low half
    asm("cvt.rn.bf16x2.f32 %0, %2, %1;" : "=r"(r) : "f"(lo), "f"(hi));
    return r;
}
__device__ __forceinline__ void ldsm_x4(uint32_t& r0, uint32_t& r1, uint32_t& r2, uint32_t& r3,
                                        uint32_t addr) {
    asm volatile("ldmatrix.sync.aligned.m8n8.x4.shared.b16 {%0,%1,%2,%3}, [%4];"
                 : "=r"(r0), "=r"(r1), "=r"(r2), "=r"(r3) : "r"(addr));
}
__device__ __forceinline__ void mma_bf16(float& c0, float& c1, float& c2, float& c3,
                                         uint32_t a0, uint32_t a1, uint32_t a2, uint32_t a3,
                                         uint32_t b0, uint32_t b1) {
    asm volatile("mma.sync.aligned.m16n8k16.row.col.f32.bf16.bf16.f32 "
                 "{%0,%1,%2,%3}, {%4,%5,%6,%7}, {%8,%9}, {%0,%1,%2,%3};"
                 : "+f"(c0), "+f"(c1), "+f"(c2), "+f"(c3)
                 : "r"(a0), "r"(a1), "r"(a2), "r"(a3), "r"(b0), "r"(b1));
}
__device__ __forceinline__ void cp16(uint32_t smem_dst, const void* gsrc) {
    asm volatile("cp.async.cg.shared.global [%0], [%1], 16;" :: "r"(smem_dst), "l"(gsrc));
}
__device__ __forceinline__ void cp_commit() { asm volatile("cp.async.commit_group;"); }
__device__ __forceinline__ void cp_wait0()  { asm volatile("cp.async.wait_group 0;" ::: "memory"); }

// ---------------------------------------------------------------------------
// Kernel 1: norms (exact reference order) + bf16 conversions + scratch init
// ---------------------------------------------------------------------------
__global__ void norms_kernel(const float* __restrict__ x,
                             const float* __restrict__ cb) {
    int i = blockIdx.x * blockDim.x + threadIdx.x;
    if (i < K_CODES) {
        const float4* r = reinterpret_cast<const float4*>(cb) + (size_t)i * 64;
        unsigned* cbw = g_cbb + (size_t)i * 128;
        float s = 0.0f;
#pragma unroll
        for (int d = 0; d < 64; ++d) {
            float4 v = r[d];
            s = __fadd_rn(s, __fmul_rn(v.x, v.x));
            s = __fadd_rn(s, __fmul_rn(v.y, v.y));
            s = __fadd_rn(s, __fmul_rn(v.z, v.z));
            s = __fadd_rn(s, __fmul_rn(v.w, v.w));
            cbw[d * 2 + 0] = pack_bf16x2(v.x, v.y);
            cbw[d * 2 + 1] = pack_bf16x2(v.z, v.w);
        }
        g_cc[i] = s;
    }
    if (i < N_ROWS) {
        g_pack[i] = ~0ULL;
        g_cnt[i] = 0;
        const float4* r = reinterpret_cast<const float4*>(x) + (size_t)i * 64;
        unsigned* xbw = g_xbb + (size_t)i * 128;
        float s = 0.0f;
#pragma unroll
        for (int d = 0; d < 64; ++d) {
            float4 v = r[d];
            s = __fadd_rn(s, __fmul_rn(v.x, v.x));
            s = __fadd_rn(s, __fmul_rn(v.y, v.y));
            s = __fadd_rn(s, __fmul_rn(v.z, v.z));
            s = __fadd_rn(s, __fmul_rn(v.w, v.w));
            xbw[d * 2 + 0] = pack_bf16x2(v.x, v.y);
            xbw[d * 2 + 1] = pack_bf16x2(v.z, v.w);
        }
        g_xx[i] = s;
    }
}

// ---------------------------------------------------------------------------
// Kernel 2: bf16 tensor-core screening (mma.sync m16n8k16).
// CTA: 128 rows x 4096 codes. A persistent in smem; B double-buffered via
// cp.async. 8 warps, warp tile 16 rows x 64 codes.
// Fragment layout (row.col): lane l covers rows {l/4, l/4+8} (relative to
// warp base) and cols {(l%4)*2, +1} of each 8-col tile.
// Epilogue: dists in regs, per-row min via shfl over the 4 covering lanes,
// push candidates within MARGIN of the running row min. Winner-capture proof:
// bf16 screen error << MARGIN/2, so the exact argmin is always pushed.
// ---------------------------------------------------------------------------
__global__ __launch_bounds__(256, 1)
void screen_kernel() {
    extern __shared__ __align__(16) char smem[];
    __shared__ float ccs[2][SCR_NC];

    const int tid  = threadIdx.x;
    const int wid  = tid >> 5;
    const int lane = tid & 31;
    const int rowBase = blockIdx.x * SCR_M;

    const uint32_t A_base  = smem_u32(smem);
    const uint32_t B_base0 = A_base + A_BYTES;

    // ---- load A (x rows, bf16) into smem, padded rows of 264 bf16
    {
        const int row = tid >> 1, half = tid & 1;
        const uint4* src = reinterpret_cast<const uint4*>(g_xbb) + (size_t)(rowBase + row) * 32 + half * 16;
        uint4* dst = reinterpret_cast<uint4*>(smem) + (size_t)row * 33 + half * 16;
#pragma unroll
        for (int j = 0; j < 16; ++j) dst[j] = src[j];
    }

    // ---- B chunk loader (cp.async): 64 codes x 256 bf16 = 2048 x 16B
    auto issue_copy = [&](int chunk, int buf) {
        const uint4* src = reinterpret_cast<const uint4*>(g_cbb) + (size_t)chunk * SCR_NC * 32;
        const uint32_t dstb = B_base0 + buf * B_BYTES;
#pragma unroll
        for (int it = 0; it < 8; ++it) {
            const int idx = tid + it * 256;
            const int r = idx >> 5, seg = idx & 31;
            cp16(dstb + r * ROW_B + seg * 16, src + (size_t)r * 32 + seg);
        }
        if (tid < 16)
            cp16(smem_u32(&ccs[buf][0]) + tid * 16,
                 (const char*)g_cc + (size_t)chunk * SCR_NC * 4 + tid * 16);
        cp_commit();
    };

    issue_copy(0, 0);

    // per-lane ldmatrix byte offsets (verified against PTX ISA fragment maps)
    const uint32_t a_off = (uint32_t)((wid * 16 + (lane & 7) + ((lane & 8) ? 8 : 0)) * ROW_B
                                      + ((lane & 16) ? 16 : 0));
    const uint32_t b_off = (uint32_t)(((lane & 7) + ((lane & 16) ? 8 : 0)) * ROW_B
                                      + ((lane & 8) ? 16 : 0));

    const int rowA = rowBase + wid * 16 + (lane >> 2);
    const int rowB = rowA + 8;
    const float xxA = g_xx[rowA];
    const float xxB = g_xx[rowB];
    float runA = FINF, runB = FINF;

    for (int c = 0; c < SCR_NCHUNK; ++c) {
        cp_wait0();
        __syncthreads();
        if (c + 1 < SCR_NCHUNK) issue_copy(c + 1, (c + 1) & 1);
        const uint32_t Bb = B_base0 + (c & 1) * B_BYTES;

        float acc[8][4];
#pragma unroll
        for (int t = 0; t < 8; ++t)
#pragma unroll
            for (int e = 0; e < 4; ++e) acc[t][e] = 0.0f;

#pragma unroll
        for (int s = 0; s < 16; ++s) {
            uint32_t a0, a1, a2, a3;
            ldsm_x4(a0, a1, a2, a3, A_base + a_off + s * 32);
#pragma unroll
            for (int p = 0; p < 4; ++p) {
                uint32_t b0, b1, b2, b3;
                ldsm_x4(b0, b1, b2, b3, Bb + b_off + p * (16 * ROW_B) + s * 32);
                mma_bf16(acc[2 * p][0], acc[2 * p][1], acc[2 * p][2], acc[2 * p][3],
                         a0, a1, a2, a3, b0, b1);
                mma_bf16(acc[2 * p + 1][0], acc[2 * p + 1][1], acc[2 * p + 1][2], acc[2 * p + 1][3],
                         a0, a1, a2, a3, b2, b3);
            }
        }

        // ---- epilogue: dists + row-min + candidate pushes
        const int cbase = c * SCR_NC;
        float dA[16], dB[16];
#pragma unroll
        for (int t = 0; t < 8; ++t)
#pragma unroll
            for (int e = 0; e < 2; ++e) {
                const float ccv = ccs[c & 1][t * 8 + (lane & 3) * 2 + e];
                dA[t * 2 + e] = __fmaf_rn(-2.0f, acc[t][e],     xxA + ccv);
                dB[t * 2 + e] = __fmaf_rn(-2.0f, acc[t][2 + e], xxB + ccv);
            }

        float mA = dA[0], mB = dB[0];
#pragma unroll
        for (int k = 1; k < 16; ++k) { mA = fminf(mA, dA[k]); mB = fminf(mB, dB[k]); }
        mA = fminf(mA, __shfl_xor_sync(0xffffffffu, mA, 1));
        mA = fminf(mA, __shfl_xor_sync(0xffffffffu, mA, 2));
        mB = fminf(mB, __shfl_xor_sync(0xffffffffu, mB, 1));
        mB = fminf(mB, __shfl_xor_sync(0xffffffffu, mB, 2));

        const float nmA = fminf(runA, mA);
        const float nmB = fminf(runB, mB);
        if (mA < runA + MARGIN) {
#pragma unroll
            for (int k = 0; k < 16; ++k)
                if (dA[k] < nmA + MARGIN) {
                    const int code = cbase + (k >> 1) * 8 + (lane & 3) * 2 + (k & 1);
                    const int slot = atomicAdd(&g_cnt[rowA], 1);
                    if (slot < CAND_CAP) g_cand[(size_t)rowA * CAND_CAP + slot] = code;
                }
        }
        if (mB < runB + MARGIN) {
#pragma unroll
            for (int k = 0; k < 16; ++k)
                if (dB[k] < nmB + MARGIN) {
                    const int code = cbase + (k >> 1) * 8 + (lane & 3) * 2 + (k & 1);
                    const int slot = atomicAdd(&g_cnt[rowB], 1);
                    if (slot < CAND_CAP) g_cand[(size_t)rowB * CAND_CAP + slot] = code;
                }
        }
        runA = nmA;
        runB = nmB;
    }
}

// ---------------------------------------------------------------------------
// Kernel 3: exact rescore (bitwise-identical fp32 chain to the R3 kernel
// that matched the reference exactly: sequential d, single accumulator,
// reference dist rounding, lowest-index tie-break via packed atomicMin).
// ---------------------------------------------------------------------------
__global__ void rescore_kernel(const float* __restrict__ x,
                               const float* __restrict__ cb) {
    const int gid = blockIdx.x * blockDim.x + threadIdx.x;
    const int row = gid >> 6;
    const int slot = gid & 63;
    if (slot >= g_cnt[row]) return;
    const int code = g_cand[(size_t)row * CAND_CAP + slot];

    const float4* xr = reinterpret_cast<const float4*>(x) + (size_t)row * 64;
    const float4* cr = reinterpret_cast<const float4*>(cb) + (size_t)code * 64;
    float s = 0.0f;
#pragma unroll 8
    for (int i = 0; i < 64; ++i) {
        float4 a = xr[i], b = cr[i];
        s = __fmaf_rn(a.x, b.x, s);
        s = __fmaf_rn(a.y, b.y, s);
        s = __fmaf_rn(a.z, b.z, s);
        s = __fmaf_rn(a.w, b.w, s);
    }
    const float dist = __fadd_rn(__fadd_rn(g_xx[row], g_cc[code]), __fmul_rn(-2.0f, s));
    const ull key = ((ull)__float_as_uint(dist) << 32) | (unsigned)code;
    atomicMin(&g_pack[row], key);
}

// ---------------------------------------------------------------------------
// Kernel 4: out = x + (codebook[best] - x)  (reference STE rounding)
// ---------------------------------------------------------------------------
__global__ void gather_kernel(const float* __restrict__ x,
                              const float* __restrict__ cb,
                              float* __restrict__ out) {
    const int idx = blockIdx.x * blockDim.x + threadIdx.x;
    const int row = idx >> 6;
    const int seg = idx & 63;
    const int code = (int)(unsigned)(g_pack[row] & 0xFFFFFFFFULL);
    float4 c = reinterpret_cast<const float4*>(cb)[(size_t)code * 64 + seg];
    float4 v = reinterpret_cast<const float4*>(x)[idx];
    float4 o;
    o.x = __fadd_rn(v.x, __fsub_rn(c.x, v.x));
    o.y = __fadd_rn(v.y, __fsub_rn(c.y, v.y));
    o.z = __fadd_rn(v.z, __fsub_rn(c.z, v.z));
    o.w = __fadd_rn(v.w, __fsub_rn(c.w, v.w));
    reinterpret_cast<float4*>(out)[idx] = o;
}

// ---------------------------------------------------------------------------
extern "C" void kernel_launch(void* const* d_in, const int* in_sizes, int n_in,
                              void* d_out, int out_size) {
    const float* x  = (const float*)d_in[0];
    const float* cb = (const float*)d_in[1];
    if (n_in >= 2 && in_sizes[0] == K_CODES * D_DIM && in_sizes[1] == N_ROWS * D_DIM) {
        const float* t = x; x = cb; cb = t;
    }
    float* out = (float*)d_out;

    const int scr_smem = A_BYTES + 2 * B_BYTES;   // 135168
    cudaFuncSetAttribute(screen_kernel, cudaFuncAttributeMaxDynamicSharedMemorySize, scr_smem);

    norms_kernel<<<(N_ROWS + 255) / 256, 256>>>(x, cb);
    screen_kernel<<<N_ROWS / SCR_M, 256, scr_smem>>>();
    rescore_kernel<<<(N_ROWS * CAND_CAP) / 256, 256>>>(x, cb);
    gather_kernel<<<(N_ROWS * 64) / 256, 256>>>(x, cb, out);
}

// round 10
// speedup vs baseline: 3.8859x; 1.2145x over previous
#include <cuda_runtime.h>
#include <cuda_bf16.h>
#include <cstdint>

typedef unsigned long long ull;

#define N_ROWS 32768
#define K_CODES 4096
#define D_DIM   256

#define SCR_M 128                 // rows per screening CTA
#define SCR_NC 32                 // codes per chunk (halved for occupancy 2)
#define SCR_NCHUNK (K_CODES / SCR_NC)   // 128
#define ROW_B 528                 // smem row stride bytes: conflict-free ldmatrix
#define A_BYTES (SCR_M * ROW_B)   // 67584
#define B_BYTES (SCR_NC * ROW_B)  // 16896
#define CAND_CAP 64
#define MARGIN 4e-4f
#define FINF 3.4028235e38f

// Scratch (device globals; no allocation APIs allowed)
__device__ float g_cc[K_CODES];
__device__ float g_xx[N_ROWS];
__device__ ull   g_pack[N_ROWS];
__device__ __align__(128) unsigned g_cbb[K_CODES * D_DIM / 2];  // codebook bf16x2
__device__ __align__(128) unsigned g_xbb[N_ROWS * D_DIM / 2];   // x bf16x2
__device__ int   g_cand[N_ROWS * CAND_CAP];
__device__ int   g_cnt[N_ROWS];

// ---------------------------------------------------------------------------
// helpers (all base-ISA: portable to plain sm_100 target; NO tcgen05)
// ---------------------------------------------------------------------------
__device__ __forceinline__ uint32_t smem_u32(const void* p) {
    uint32_t a;
    asm("{ .reg .u64 t; cvta.to.shared.u64 t, %1; cvt.u32.u64 %0, t; }" : "=r"(a) : "l"(p));
    return a;
}
__device__ __forceinline__ uint32_t pack_bf16x2(float lo, float hi) {
    uint32_t r;   // cvt d, a, b packs a into high half, b into low half
    asm("cvt.rn.bf16x2.f32 %0, %2, %1;" : "=r"(r) : "f"(lo), "f"(hi));
    return r;
}
__device__ __forceinline__ void ldsm_x4(uint32_t& r0, uint32_t& r1, uint32_t& r2, uint32_t& r3,
                                        uint32_t addr) {
    asm volatile("ldmatrix.sync.aligned.m8n8.x4.shared.b16 {%0,%1,%2,%3}, [%4];"
                 : "=r"(r0), "=r"(r1), "=r"(r2), "=r"(r3) : "r"(addr));
}
__device__ __forceinline__ void mma_bf16(float& c0, float& c1, float& c2, float& c3,
                                         uint32_t a0, uint32_t a1, uint32_t a2, uint32_t a3,
                                         uint32_t b0, uint32_t b1) {
    asm volatile("mma.sync.aligned.m16n8k16.row.col.f32.bf16.bf16.f32 "
                 "{%0,%1,%2,%3}, {%4,%5,%6,%7}, {%8,%9}, {%0,%1,%2,%3};"
                 : "+f"(c0), "+f"(c1), "+f"(c2), "+f"(c3)
                 : "r"(a0), "r"(a1), "r"(a2), "r"(a3), "r"(b0), "r"(b1));
}
__device__ __forceinline__ void cp16(uint32_t smem_dst, const void* gsrc) {
    asm volatile("cp.async.cg.shared.global [%0], [%1], 16;" :: "r"(smem_dst), "l"(gsrc));
}
__device__ __forceinline__ void cp_commit() { asm volatile("cp.async.commit_group;"); }
__device__ __forceinline__ void cp_wait0()  { asm volatile("cp.async.wait_group 0;" ::: "memory"); }

// ---------------------------------------------------------------------------
// Kernel 1: norms (exact reference order) + bf16 conversions + scratch init
// ---------------------------------------------------------------------------
__global__ void norms_kernel(const float* __restrict__ x,
                             const float* __restrict__ cb) {
    int i = blockIdx.x * blockDim.x + threadIdx.x;
    if (i < K_CODES) {
        const float4* r = reinterpret_cast<const float4*>(cb) + (size_t)i * 64;
        unsigned* cbw = g_cbb + (size_t)i * 128;
        float s = 0.0f;
#pragma unroll
        for (int d = 0; d < 64; ++d) {
            float4 v = r[d];
            s = __fadd_rn(s, __fmul_rn(v.x, v.x));
            s = __fadd_rn(s, __fmul_rn(v.y, v.y));
            s = __fadd_rn(s, __fmul_rn(v.z, v.z));
            s = __fadd_rn(s, __fmul_rn(v.w, v.w));
            cbw[d * 2 + 0] = pack_bf16x2(v.x, v.y);
            cbw[d * 2 + 1] = pack_bf16x2(v.z, v.w);
        }
        g_cc[i] = s;
    }
    if (i < N_ROWS) {
        g_pack[i] = ~0ULL;
        g_cnt[i] = 0;
        const float4* r = reinterpret_cast<const float4*>(x) + (size_t)i * 64;
        unsigned* xbw = g_xbb + (size_t)i * 128;
        float s = 0.0f;
#pragma unroll
        for (int d = 0; d < 64; ++d) {
            float4 v = r[d];
            s = __fadd_rn(s, __fmul_rn(v.x, v.x));
            s = __fadd_rn(s, __fmul_rn(v.y, v.y));
            s = __fadd_rn(s, __fmul_rn(v.z, v.z));
            s = __fadd_rn(s, __fmul_rn(v.w, v.w));
            xbw[d * 2 + 0] = pack_bf16x2(v.x, v.y);
            xbw[d * 2 + 1] = pack_bf16x2(v.z, v.w);
        }
        g_xx[i] = s;
    }
}

// ---------------------------------------------------------------------------
// Kernel 2: bf16 tensor-core screening (mma.sync m16n8k16), occupancy 2.
// CTA: 128 rows x 4096 codes in 128 chunks of 32 codes. A persistent in
// smem; B double-buffered via cp.async. 8 warps, warp tile 16 rows x 32
// codes. smem = 67.6K(A) + 2x16.9K(B) = 101.4KB -> 2 CTAs/SM; all 256 CTAs
// resident (no wave quantization).
// Fragment layout (row.col): lane l covers rows {l/4, l/4+8} (relative to
// warp base) and cols {(l%4)*2, +1} of each 8-col tile.
// ---------------------------------------------------------------------------
__global__ __launch_bounds__(256, 2)
void screen_kernel() {
    extern __shared__ __align__(16) char smem[];
    __shared__ float ccs[2][SCR_NC];

    const int tid  = threadIdx.x;
    const int wid  = tid >> 5;
    const int lane = tid & 31;
    const int rowBase = blockIdx.x * SCR_M;

    const uint32_t A_base  = smem_u32(smem);
    const uint32_t B_base0 = A_base + A_BYTES;

    // ---- load A (x rows, bf16) into smem, padded rows of 264 bf16
    {
        const int row = tid >> 1, half = tid & 1;
        const uint4* src = reinterpret_cast<const uint4*>(g_xbb) + (size_t)(rowBase + row) * 32 + half * 16;
        uint4* dst = reinterpret_cast<uint4*>(smem) + (size_t)row * 33 + half * 16;
#pragma unroll
        for (int j = 0; j < 16; ++j) dst[j] = src[j];
    }

    // ---- B chunk loader (cp.async): 32 codes x 256 bf16 = 1024 x 16B
    auto issue_copy = [&](int chunk, int buf) {
        const uint4* src = reinterpret_cast<const uint4*>(g_cbb) + (size_t)chunk * SCR_NC * 32;
        const uint32_t dstb = B_base0 + buf * B_BYTES;
#pragma unroll
        for (int it = 0; it < 4; ++it) {
            const int idx = tid + it * 256;
            const int r = idx >> 5, seg = idx & 31;
            cp16(dstb + r * ROW_B + seg * 16, src + (size_t)r * 32 + seg);
        }
        if (tid < 8)
            cp16(smem_u32(&ccs[buf][0]) + tid * 16,
                 (const char*)g_cc + (size_t)chunk * SCR_NC * 4 + tid * 16);
        cp_commit();
    };

    issue_copy(0, 0);

    // per-lane ldmatrix byte offsets (verified against PTX ISA fragment maps)
    const uint32_t a_off = (uint32_t)((wid * 16 + (lane & 7) + ((lane & 8) ? 8 : 0)) * ROW_B
                                      + ((lane & 16) ? 16 : 0));
    const uint32_t b_off = (uint32_t)(((lane & 7) + ((lane & 16) ? 8 : 0)) * ROW_B
                                      + ((lane & 8) ? 16 : 0));

    const int rowA = rowBase + wid * 16 + (lane >> 2);
    const int rowB = rowA + 8;
    const float xxA = g_xx[rowA];
    const float xxB = g_xx[rowB];
    float runA = FINF, runB = FINF;

    for (int c = 0; c < SCR_NCHUNK; ++c) {
        cp_wait0();
        __syncthreads();
        if (c + 1 < SCR_NCHUNK) issue_copy(c + 1, (c + 1) & 1);
        const uint32_t Bb = B_base0 + (c & 1) * B_BYTES;

        float acc[4][4];
#pragma unroll
        for (int t = 0; t < 4; ++t)
#pragma unroll
            for (int e = 0; e < 4; ++e) acc[t][e] = 0.0f;

#pragma unroll
        for (int s = 0; s < 16; ++s) {
            uint32_t a0, a1, a2, a3;
            ldsm_x4(a0, a1, a2, a3, A_base + a_off + s * 32);
#pragma unroll
            for (int p = 0; p < 2; ++p) {
                uint32_t b0, b1, b2, b3;
                ldsm_x4(b0, b1, b2, b3, Bb + b_off + p * (16 * ROW_B) + s * 32);
                mma_bf16(acc[2 * p][0], acc[2 * p][1], acc[2 * p][2], acc[2 * p][3],
                         a0, a1, a2, a3, b0, b1);
                mma_bf16(acc[2 * p + 1][0], acc[2 * p + 1][1], acc[2 * p + 1][2], acc[2 * p + 1][3],
                         a0, a1, a2, a3, b2, b3);
            }
        }

        // ---- epilogue: per-row chunk min, then (rare) recompute-and-push
        const int cbase = c * SCR_NC;
        float mA = FINF, mB = FINF;
#pragma unroll
        for (int t = 0; t < 4; ++t)
#pragma unroll
            for (int e = 0; e < 2; ++e) {
                const float ccv = ccs[c & 1][t * 8 + (lane & 3) * 2 + e];
                mA = fminf(mA, __fmaf_rn(-2.0f, acc[t][e],     xxA + ccv));
                mB = fminf(mB, __fmaf_rn(-2.0f, acc[t][2 + e], xxB + ccv));
            }
        mA = fminf(mA, __shfl_xor_sync(0xffffffffu, mA, 1));
        mA = fminf(mA, __shfl_xor_sync(0xffffffffu, mA, 2));
        mB = fminf(mB, __shfl_xor_sync(0xffffffffu, mB, 1));
        mB = fminf(mB, __shfl_xor_sync(0xffffffffu, mB, 2));

        const float nmA = fminf(runA, mA);
        const float nmB = fminf(runB, mB);
        if (mA < runA + MARGIN) {
#pragma unroll
            for (int t = 0; t < 4; ++t)
#pragma unroll
                for (int e = 0; e < 2; ++e) {
                    const float ccv = ccs[c & 1][t * 8 + (lane & 3) * 2 + e];
                    const float d = __fmaf_rn(-2.0f, acc[t][e], xxA + ccv);
                    if (d < nmA + MARGIN) {
                        const int slot = atomicAdd(&g_cnt[rowA], 1);
                        if (slot < CAND_CAP)
                            g_cand[(size_t)rowA * CAND_CAP + slot] =
                                cbase + t * 8 + (lane & 3) * 2 + e;
                    }
                }
        }
        if (mB < runB + MARGIN) {
#pragma unroll
            for (int t = 0; t < 4; ++t)
#pragma unroll
                for (int e = 0; e < 2; ++e) {
                    const float ccv = ccs[c & 1][t * 8 + (lane & 3) * 2 + e];
                    const float d = __fmaf_rn(-2.0f, acc[t][2 + e], xxB + ccv);
                    if (d < nmB + MARGIN) {
                        const int slot = atomicAdd(&g_cnt[rowB], 1);
                        if (slot < CAND_CAP)
                            g_cand[(size_t)rowB * CAND_CAP + slot] =
                                cbase + t * 8 + (lane & 3) * 2 + e;
                    }
                }
        }
        runA = nmA;
        runB = nmB;
    }
}

// ---------------------------------------------------------------------------
// Kernel 3: exact rescore (bitwise-identical fp32 chain to the R3 kernel
// that matched the reference exactly: sequential d, single accumulator,
// reference dist rounding, lowest-index tie-break via packed atomicMin).
// ---------------------------------------------------------------------------
__global__ void rescore_kernel(const float* __restrict__ x,
                               const float* __restrict__ cb) {
    const int gid = blockIdx.x * blockDim.x + threadIdx.x;
    const int row = gid >> 6;
    const int slot = gid & 63;
    if (slot >= g_cnt[row]) return;
    const int code = g_cand[(size_t)row * CAND_CAP + slot];

    const float4* xr = reinterpret_cast<const float4*>(x) + (size_t)row * 64;
    const float4* cr = reinterpret_cast<const float4*>(cb) + (size_t)code * 64;
    float s = 0.0f;
#pragma unroll 8
    for (int i = 0; i < 64; ++i) {
        float4 a = xr[i], b = cr[i];
        s = __fmaf_rn(a.x, b.x, s);
        s = __fmaf_rn(a.y, b.y, s);
        s = __fmaf_rn(a.z, b.z, s);
        s = __fmaf_rn(a.w, b.w, s);
    }
    const float dist = __fadd_rn(__fadd_rn(g_xx[row], g_cc[code]), __fmul_rn(-2.0f, s));
    const ull key = ((ull)__float_as_uint(dist) << 32) | (unsigned)code;
    atomicMin(&g_pack[row], key);
}

// ---------------------------------------------------------------------------
// Kernel 4: out = x + (codebook[best] - x)  (reference STE rounding)
// ---------------------------------------------------------------------------
__global__ void gather_kernel(const float* __restrict__ x,
                              const float* __restrict__ cb,
                              float* __restrict__ out) {
    const int idx = blockIdx.x * blockDim.x + threadIdx.x;
    const int row = idx >> 6;
    const int seg = idx & 63;
    const int code = (int)(unsigned)(g_pack[row] & 0xFFFFFFFFULL);
    float4 c = reinterpret_cast<const float4*>(cb)[(size_t)code * 64 + seg];
    float4 v = reinterpret_cast<const float4*>(x)[idx];
    float4 o;
    o.x = __fadd_rn(v.x, __fsub_rn(c.x, v.x));
    o.y = __fadd_rn(v.y, __fsub_rn(c.y, v.y));
    o.z = __fadd_rn(v.z, __fsub_rn(c.z, v.z));
    o.w = __fadd_rn(v.w, __fsub_rn(c.w, v.w));
    reinterpret_cast<float4*>(out)[idx] = o;
}

// ---------------------------------------------------------------------------
extern "C" void kernel_launch(void* const* d_in, const int* in_sizes, int n_in,
                              void* d_out, int out_size) {
    const float* x  = (const float*)d_in[0];
    const float* cb = (const float*)d_in[1];
    if (n_in >= 2 && in_sizes[0] == K_CODES * D_DIM && in_sizes[1] == N_ROWS * D_DIM) {
        const float* t = x; x = cb; cb = t;
    }
    float* out = (float*)d_out;

    const int scr_smem = A_BYTES + 2 * B_BYTES;   // 101376 -> 2 CTAs/SM
    cudaFuncSetAttribute(screen_kernel, cudaFuncAttributeMaxDynamicSharedMemorySize, scr_smem);

    norms_kernel<<<(N_ROWS + 255) / 256, 256>>>(x, cb);
    screen_kernel<<<N_ROWS / SCR_M, 256, scr_smem>>>();
    rescore_kernel<<<(N_ROWS * CAND_CAP) / 256, 256>>>(x, cb);
    gather_kernel<<<(N_ROWS * 64) / 256, 256>>>(x, cb, out);
}

// round 13
// speedup vs baseline: 4.4827x; 1.1536x over previous
#include <cuda_runtime.h>
#include <cuda_bf16.h>
#include <cstdint>

typedef unsigned long long ull;

#define N_ROWS 32768
#define K_CODES 4096
#define D_DIM   256

#define SCR_M 128                 // rows per screening CTA
#define SCR_NC 32                 // codes per chunk
#define SCR_NCHUNK (K_CODES / SCR_NC)   // 128
#define ROW_B 528                 // smem row stride bytes: conflict-free ldmatrix
#define A_BYTES (SCR_M * ROW_B)   // 67584 (A staging; B buffers reuse this space)
#define B_BYTES (SCR_NC * ROW_B)  // 16896
#define CAND_CAP 64
#define MARGIN 4e-4f
#define FINF 3.4028235e38f

// Scratch (device globals; no allocation APIs allowed)
__device__ float g_cc[K_CODES];
__device__ float g_xx[N_ROWS];
__device__ ull   g_pack[N_ROWS];
__device__ __align__(128) unsigned g_cbb[K_CODES * D_DIM / 2];  // codebook bf16x2
__device__ __align__(128) unsigned g_xbb[N_ROWS * D_DIM / 2];   // x bf16x2
__device__ int   g_cand[N_ROWS * CAND_CAP];
__device__ int   g_cnt[N_ROWS];

// ---------------------------------------------------------------------------
// helpers (all base-ISA: portable to plain sm_100 target; NO tcgen05)
// ---------------------------------------------------------------------------
__device__ __forceinline__ uint32_t smem_u32(const void* p) {
    uint32_t a;
    asm("{ .reg .u64 t; cvta.to.shared.u64 t, %1; cvt.u32.u64 %0, t; }" : "=r"(a) : "l"(p));
    return a;
}
__device__ __forceinline__ uint32_t pack_bf16x2(float lo, float hi) {
    uint32_t r;   // cvt d, a, b packs a into high half, b into low half
    asm("cvt.rn.bf16x2.f32 %0, %2, %1;" : "=r"(r) : "f"(lo), "f"(hi));
    return r;
}
__device__ __forceinline__ void ldsm_x4(uint32_t& r0, uint32_t& r1, uint32_t& r2, uint32_t& r3,
                                        uint32_t addr) {
    asm volatile("ldmatrix.sync.aligned.m8n8.x4.shared.b16 {%0,%1,%2,%3}, [%4];"
                 : "=r"(r0), "=r"(r1), "=r"(r2), "=r"(r3) : "r"(addr));
}
__device__ __forceinline__ void mma_bf16(float& c0, float& c1, float& c2, float& c3,
                                         uint32_t a0, uint32_t a1, uint32_t a2, uint32_t a3,
                                         uint32_t b0, uint32_t b1) {
    asm volatile("mma.sync.aligned.m16n8k16.row.col.f32.bf16.bf16.f32 "
                 "{%0,%1,%2,%3}, {%4,%5,%6,%7}, {%8,%9}, {%0,%1,%2,%3};"
                 : "+f"(c0), "+f"(c1), "+f"(c2), "+f"(c3)
                 : "r"(a0), "r"(a1), "r"(a2), "r"(a3), "r"(b0), "r"(b1));
}
__device__ __forceinline__ void cp16(uint32_t smem_dst, const void* gsrc) {
    asm volatile("cp.async.cg.shared.global [%0], [%1], 16;" :: "r"(smem_dst), "l"(gsrc));
}
__device__ __forceinline__ void cp_commit() { asm volatile("cp.async.commit_group;"); }
__device__ __forceinline__ void cp_wait0()  { asm volatile("cp.async.wait_group 0;" ::: "memory"); }

// ---------------------------------------------------------------------------
// Kernel 1: norms (exact reference order) + bf16 conversions + scratch init
// ---------------------------------------------------------------------------
__global__ void norms_kernel(const float* __restrict__ x,
                             const float* __restrict__ cb) {
    int i = blockIdx.x * blockDim.x + threadIdx.x;
    if (i < K_CODES) {
        const float4* r = reinterpret_cast<const float4*>(cb) + (size_t)i * 64;
        unsigned* cbw = g_cbb + (size_t)i * 128;
        float s = 0.0f;
#pragma unroll
        for (int d = 0; d < 64; ++d) {
            float4 v = r[d];
            s = __fadd_rn(s, __fmul_rn(v.x, v.x));
            s = __fadd_rn(s, __fmul_rn(v.y, v.y));
            s = __fadd_rn(s, __fmul_rn(v.z, v.z));
            s = __fadd_rn(s, __fmul_rn(v.w, v.w));
            cbw[d * 2 + 0] = pack_bf16x2(v.x, v.y);
            cbw[d * 2 + 1] = pack_bf16x2(v.z, v.w);
        }
        g_cc[i] = s;
    }
    if (i < N_ROWS) {
        g_pack[i] = ~0ULL;
        g_cnt[i] = 0;
        const float4* r = reinterpret_cast<const float4*>(x) + (size_t)i * 64;
        unsigned* xbw = g_xbb + (size_t)i * 128;
        float s = 0.0f;
#pragma unroll
        for (int d = 0; d < 64; ++d) {
            float4 v = r[d];
            s = __fadd_rn(s, __fmul_rn(v.x, v.x));
            s = __fadd_rn(s, __fmul_rn(v.y, v.y));
            s = __fadd_rn(s, __fmul_rn(v.z, v.z));
            s = __fadd_rn(s, __fmul_rn(v.w, v.w));
            xbw[d * 2 + 0] = pack_bf16x2(v.x, v.y);
            xbw[d * 2 + 1] = pack_bf16x2(v.z, v.w);
        }
        g_xx[i] = s;
    }
}

// ---------------------------------------------------------------------------
// Kernel 2: bf16 tensor-core screening (mma.sync m16n8k16), occupancy 2,
// A FRAGMENTS HOISTED TO REGISTERS.
// Prologue: stage A (128 rows bf16) in smem once, each warp ldmatrix's its
// 16 rows x 16 k-steps into af[16][4] (64 regs), then the smem region is
// reused for the B double buffer (smem total 67.6KB).
// Chunk loop (128 chunks of 32 codes): 32 B-ldsm + 64 HMMA per warp
// (A-ldsm eliminated). Per-code arithmetic bitwise-identical to R10.
// ---------------------------------------------------------------------------
__global__ __launch_bounds__(256, 2)
void screen_kernel() {
    extern __shared__ __align__(16) char smem[];
    __shared__ float ccs[2][SCR_NC];

    const int tid  = threadIdx.x;
    const int wid  = tid >> 5;
    const int lane = tid & 31;
    const int rowBase = blockIdx.x * SCR_M;

    const uint32_t S_base = smem_u32(smem);   // A staging, then B buffers

    // ---- stage A (x rows, bf16) via cp.async: 128 rows x 32 x 16B
    {
#pragma unroll
        for (int it = 0; it < 16; ++it) {
            const int idx = tid + it * 256;       // 0..4095
            const int r = idx >> 5, seg = idx & 31;
            cp16(S_base + r * ROW_B + seg * 16,
                 (const char*)g_xbb + (size_t)(rowBase + r) * 512 + seg * 16);
        }
        cp_commit();
        cp_wait0();
        __syncthreads();
    }

    // per-lane ldmatrix byte offsets (verified against PTX ISA fragment maps)
    const uint32_t a_off = (uint32_t)((wid * 16 + (lane & 7) + ((lane & 8) ? 8 : 0)) * ROW_B
                                      + ((lane & 16) ? 16 : 0));
    const uint32_t b_off = (uint32_t)(((lane & 7) + ((lane & 16) ? 8 : 0)) * ROW_B
                                      + ((lane & 8) ? 16 : 0));

    // ---- hoist A fragments into registers: af[16 k-steps][4 regs]
    uint32_t af[16][4];
#pragma unroll
    for (int s = 0; s < 16; ++s)
        ldsm_x4(af[s][0], af[s][1], af[s][2], af[s][3], S_base + a_off + s * 32);
    __syncthreads();   // all warps done reading A; smem now free for B

    // ---- B chunk loader (cp.async): 32 codes x 256 bf16 = 1024 x 16B
    auto issue_copy = [&](int chunk, int buf) {
        const uint4* src = reinterpret_cast<const uint4*>(g_cbb) + (size_t)chunk * SCR_NC * 32;
        const uint32_t dstb = S_base + buf * B_BYTES;
#pragma unroll
        for (int it = 0; it < 4; ++it) {
            const int idx = tid + it * 256;
            const int r = idx >> 5, seg = idx & 31;
            cp16(dstb + r * ROW_B + seg * 16, src + (size_t)r * 32 + seg);
        }
        if (tid < 8)
            cp16(smem_u32(&ccs[buf][0]) + tid * 16,
                 (const char*)g_cc + (size_t)chunk * SCR_NC * 4 + tid * 16);
        cp_commit();
    };

    issue_copy(0, 0);

    const int rowA = rowBase + wid * 16 + (lane >> 2);
    const int rowB = rowA + 8;
    const float xxA = g_xx[rowA];
    const float xxB = g_xx[rowB];
    float runA = FINF, runB = FINF;

    for (int c = 0; c < SCR_NCHUNK; ++c) {
        cp_wait0();
        __syncthreads();
        if (c + 1 < SCR_NCHUNK) issue_copy(c + 1, (c + 1) & 1);
        const uint32_t Bb = S_base + (c & 1) * B_BYTES;

        float acc[4][4];
#pragma unroll
        for (int t = 0; t < 4; ++t)
#pragma unroll
            for (int e = 0; e < 4; ++e) acc[t][e] = 0.0f;

#pragma unroll
        for (int s = 0; s < 16; ++s) {
#pragma unroll
            for (int p = 0; p < 2; ++p) {
                uint32_t b0, b1, b2, b3;
                ldsm_x4(b0, b1, b2, b3, Bb + b_off + p * (16 * ROW_B) + s * 32);
                mma_bf16(acc[2 * p][0], acc[2 * p][1], acc[2 * p][2], acc[2 * p][3],
                         af[s][0], af[s][1], af[s][2], af[s][3], b0, b1);
                mma_bf16(acc[2 * p + 1][0], acc[2 * p + 1][1], acc[2 * p + 1][2], acc[2 * p + 1][3],
                         af[s][0], af[s][1], af[s][2], af[s][3], b2, b3);
            }
        }

        // ---- epilogue: per-row chunk min, then (rare) recompute-and-push
        const int cbase = c * SCR_NC;
        float mA = FINF, mB = FINF;
#pragma unroll
        for (int t = 0; t < 4; ++t)
#pragma unroll
            for (int e = 0; e < 2; ++e) {
                const float ccv = ccs[c & 1][t * 8 + (lane & 3) * 2 + e];
                mA = fminf(mA, __fmaf_rn(-2.0f, acc[t][e],     xxA + ccv));
                mB = fminf(mB, __fmaf_rn(-2.0f, acc[t][2 + e], xxB + ccv));
            }
        mA = fminf(mA, __shfl_xor_sync(0xffffffffu, mA, 1));
        mA = fminf(mA, __shfl_xor_sync(0xffffffffu, mA, 2));
        mB = fminf(mB, __shfl_xor_sync(0xffffffffu, mB, 1));
        mB = fminf(mB, __shfl_xor_sync(0xffffffffu, mB, 2));

        const float nmA = fminf(runA, mA);
        const float nmB = fminf(runB, mB);
        if (mA < runA + MARGIN) {
#pragma unroll
            for (int t = 0; t < 4; ++t)
#pragma unroll
                for (int e = 0; e < 2; ++e) {
                    const float ccv = ccs[c & 1][t * 8 + (lane & 3) * 2 + e];
                    const float d = __fmaf_rn(-2.0f, acc[t][e], xxA + ccv);
                    if (d < nmA + MARGIN) {
                        const int slot = atomicAdd(&g_cnt[rowA], 1);
                        if (slot < CAND_CAP)
                            g_cand[(size_t)rowA * CAND_CAP + slot] =
                                cbase + t * 8 + (lane & 3) * 2 + e;
                    }
                }
        }
        if (mB < runB + MARGIN) {
#pragma unroll
            for (int t = 0; t < 4; ++t)
#pragma unroll
                for (int e = 0; e < 2; ++e) {
                    const float ccv = ccs[c & 1][t * 8 + (lane & 3) * 2 + e];
                    const float d = __fmaf_rn(-2.0f, acc[t][2 + e], xxB + ccv);
                    if (d < nmB + MARGIN) {
                        const int slot = atomicAdd(&g_cnt[rowB], 1);
                        if (slot < CAND_CAP)
                            g_cand[(size_t)rowB * CAND_CAP + slot] =
                                cbase + t * 8 + (lane & 3) * 2 + e;
                    }
                }
        }
        runA = nmA;
        runB = nmB;
    }
}

// ---------------------------------------------------------------------------
// Kernel 3: exact rescore (bitwise-identical fp32 chain to the R3 kernel
// that matched the reference exactly: sequential d, single accumulator,
// reference dist rounding, lowest-index tie-break via packed atomicMin).
// ---------------------------------------------------------------------------
__global__ void rescore_kernel(const float* __restrict__ x,
                               const float* __restrict__ cb) {
    const int gid = blockIdx.x * blockDim.x + threadIdx.x;
    const int row = gid >> 6;
    const int slot = gid & 63;
    if (slot >= g_cnt[row]) return;
    const int code = g_cand[(size_t)row * CAND_CAP + slot];

    const float4* xr = reinterpret_cast<const float4*>(x) + (size_t)row * 64;
    const float4* cr = reinterpret_cast<const float4*>(cb) + (size_t)code * 64;
    float s = 0.0f;
#pragma unroll 8
    for (int i = 0; i < 64; ++i) {
        float4 a = xr[i], b = cr[i];
        s = __fmaf_rn(a.x, b.x, s);
        s = __fmaf_rn(a.y, b.y, s);
        s = __fmaf_rn(a.z, b.z, s);
        s = __fmaf_rn(a.w, b.w, s);
    }
    const float dist = __fadd_rn(__fadd_rn(g_xx[row], g_cc[code]), __fmul_rn(-2.0f, s));
    const ull key = ((ull)__float_as_uint(dist) << 32) | (unsigned)code;
    atomicMin(&g_pack[row], key);
}

// ---------------------------------------------------------------------------
// Kernel 4: out = x + (codebook[best] - x)  (reference STE rounding)
// ---------------------------------------------------------------------------
__global__ void gather_kernel(const float* __restrict__ x,
                              const float* __restrict__ cb,
                              float* __restrict__ out) {
    const int idx = blockIdx.x * blockDim.x + threadIdx.x;
    const int row = idx >> 6;
    const int seg = idx & 63;
    const int code = (int)(unsigned)(g_pack[row] & 0xFFFFFFFFULL);
    float4 c = reinterpret_cast<const float4*>(cb)[(size_t)code * 64 + seg];
    float4 v = reinterpret_cast<const float4*>(x)[idx];
    float4 o;
    o.x = __fadd_rn(v.x, __fsub_rn(c.x, v.x));
    o.y = __fadd_rn(v.y, __fsub_rn(c.y, v.y));
    o.z = __fadd_rn(v.z, __fsub_rn(c.z, v.z));
    o.w = __fadd_rn(v.w, __fsub_rn(c.w, v.w));
    reinterpret_cast<float4*>(out)[idx] = o;
}

// ---------------------------------------------------------------------------
extern "C" void kernel_launch(void* const* d_in, const int* in_sizes, int n_in,
                              void* d_out, int out_size) {
    const float* x  = (const float*)d_in[0];
    const float* cb = (const float*)d_in[1];
    if (n_in >= 2 && in_sizes[0] == K_CODES * D_DIM && in_sizes[1] == N_ROWS * D_DIM) {
        const float* t = x; x = cb; cb = t;
    }
    float* out = (float*)d_out;

    const int scr_smem = A_BYTES;   // 67584: A staging, then B double buffer
    cudaFuncSetAttribute(screen_kernel, cudaFuncAttributeMaxDynamicSharedMemorySize, scr_smem);

    norms_kernel<<<(N_ROWS + 255) / 256, 256>>>(x, cb);
    screen_kernel<<<N_ROWS / SCR_M, 256, scr_smem>>>();
    rescore_kernel<<<(N_ROWS * CAND_CAP) / 256, 256>>>(x, cb);
    gather_kernel<<<(N_ROWS * 64) / 256, 256>>>(x, cb, out);
}